// round 4
// baseline (speedup 1.0000x reference)
#include <cuda_runtime.h>
#include <cuda_bf16.h>
#include <cstdint>

// ---------------------------------------------------------------------------
// LSTM cell, B=4096, IN=H=1024 (K=2048).
// gates[B,4H] = [x|h] @ [Wx|Wh]^T + b; then elementwise LSTM epilogue.
// Portable tensor-core path (compute_103-safe): mma.sync m16n8k16 bf16,
// bf16 hi/lo 3-term split for fp32-grade accuracy, cp.async 3-stage pipeline,
// fused epilogue (all 4 gate tiles per CTA).
// ---------------------------------------------------------------------------

#define BB   4096
#define HH   1024
#define KKT  2048
#define TM   128          // rows per CTA
#define TNH  64           // h-cols per CTA (x4 gates = 256 eff cols)
#define KC   32           // K per chunk
#define NCHUNK (KKT / KC) // 64
#define RSTRIDE 80        // smem row stride bytes (64B data + 16B pad)

#define ALO_ST (128 * RSTRIDE)             // 10240
#define B_ST   (2 * 128 * RSTRIDE)         // 20480
#define BROWS_BYTES (256 * RSTRIDE)        // 20480
#define STAGE_BYTES (B_ST + 2 * BROWS_BYTES)  // 61440
#define NSTAGE 3
#define SMEM_TOTAL (STAGE_BYTES * NSTAGE)  // 184320 (epilogue reuses: 136192)

// Pre-split operands (filled each launch; deterministic).
__device__ __nv_bfloat16 g_Ahi[(size_t)BB * KKT];
__device__ __nv_bfloat16 g_Alo[(size_t)BB * KKT];
__device__ __nv_bfloat16 g_Whi[(size_t)4 * HH * KKT];
__device__ __nv_bfloat16 g_Wlo[(size_t)4 * HH * KKT];

// ------------------------------ helpers ------------------------------------

__device__ __forceinline__ uint32_t smem_u32(const void* p) {
    uint32_t a;
    asm("{ .reg .u64 t; cvta.to.shared.u64 t, %1; cvt.u32.u64 %0, t; }" : "=r"(a) : "l"(p));
    return a;
}

__device__ __forceinline__ void cpa16(uint32_t dst, const void* src) {
    asm volatile("cp.async.cg.shared.global [%0], [%1], 16;" :: "r"(dst), "l"(src) : "memory");
}

#define CP_COMMIT() asm volatile("cp.async.commit_group;" ::: "memory")
#define CP_WAIT2()  asm volatile("cp.async.wait_group 2;" ::: "memory")

#define LDSM4(R, ADDR) \
    asm volatile("ldmatrix.sync.aligned.m8n8.x4.shared.b16 {%0,%1,%2,%3}, [%4];" \
                 : "=r"((R)[0]), "=r"((R)[1]), "=r"((R)[2]), "=r"((R)[3]) : "r"(ADDR))

#define MMA(D, A, B0, B1) \
    asm volatile("mma.sync.aligned.m16n8k16.row.col.f32.bf16.bf16.f32 " \
                 "{%0,%1,%2,%3}, {%4,%5,%6,%7}, {%8,%9}, {%0,%1,%2,%3};" \
                 : "+f"((D)[0]), "+f"((D)[1]), "+f"((D)[2]), "+f"((D)[3]) \
                 : "r"((A)[0]), "r"((A)[1]), "r"((A)[2]), "r"((A)[3]), "r"(B0), "r"(B1))

__device__ __forceinline__ float sigf(float x) {
    return __fdividef(1.0f, 1.0f + __expf(-x));
}
__device__ __forceinline__ float tanh_fast(float x) {
    return __fdividef(2.0f, 1.0f + __expf(-2.0f * x)) - 1.0f;
}

// ------------------------- pre-pass: fp32 -> bf16 hi/lo ---------------------
// A region [m,k]: k<1024 -> x, else h_prev. W region [gate,hg,k]: k<1024 -> Wx else Wh.

__global__ void __launch_bounds__(256) split_kernel(
    const float* __restrict__ x, const float* __restrict__ h,
    const float* __restrict__ Wii, const float* __restrict__ Wif,
    const float* __restrict__ Wig, const float* __restrict__ Wio,
    const float* __restrict__ Whi_, const float* __restrict__ Whf,
    const float* __restrict__ Whg, const float* __restrict__ Who) {
    const int AQ = (BB * KKT) / 4;   // float4 units in A region
    int t = blockIdx.x * 256 + threadIdx.x;

    const float* src;
    __nv_bfloat16 *hid, *lod;
    size_t e;
    if (t < AQ) {
        e = (size_t)t * 4;
        int m = t >> 9;
        int k = (int)(e & 2047);
        src = (k < 1024) ? (x + (size_t)m * 1024 + k) : (h + (size_t)m * 1024 + (k - 1024));
        hid = g_Ahi + e; lod = g_Alo + e;
    } else {
        int w = t - AQ;
        e = (size_t)w * 4;
        int gh = w >> 9;
        int k = (int)(e & 2047);
        int gate = gh >> 10;
        int hg = gh & 1023;
        const float* W;
        if (k < 1024) W = (gate == 0) ? Wii : (gate == 1) ? Wif : (gate == 2) ? Wig : Wio;
        else          W = (gate == 0) ? Whi_ : (gate == 1) ? Whf : (gate == 2) ? Whg : Who;
        src = W + (size_t)hg * 1024 + (k & 1023);
        hid = g_Whi + e; lod = g_Wlo + e;
    }

    float4 v = *(const float4*)src;
    float vv[4] = {v.x, v.y, v.z, v.w};
    uint32_t hp[2] = {0, 0}, lp[2] = {0, 0};
#pragma unroll
    for (int i = 0; i < 4; i++) {
        __nv_bfloat16 hb = __float2bfloat16(vv[i]);
        float res = vv[i] - __bfloat162float(hb);
        __nv_bfloat16 lb = __float2bfloat16(res);
        hp[i >> 1] |= (uint32_t)__bfloat16_as_ushort(hb) << ((i & 1) * 16);
        lp[i >> 1] |= (uint32_t)__bfloat16_as_ushort(lb) << ((i & 1) * 16);
    }
    *(uint2*)hid = make_uint2(hp[0], hp[1]);
    *(uint2*)lod = make_uint2(lp[0], lp[1]);
}

// ------------------------------ gmem -> smem -------------------------------

__device__ __forceinline__ void load_chunk(uint32_t stage, int m0, int h0, int k0, int tid) {
#pragma unroll
    for (int j = 0; j < 12; j++) {
        int v = j * 256 + tid;
        const __nv_bfloat16* src;
        uint32_t dst;
        if (v < 1024) {                               // A hi/lo: 2*128 rows * 4 u4
            int which = v >> 9, idx = v & 511;
            int row = idx >> 2, u = idx & 3;
            src = (which ? g_Alo : g_Ahi) + (size_t)(m0 + row) * KKT + k0 + u * 8;
            dst = stage + which * ALO_ST + row * RSTRIDE + u * 16;
        } else {                                      // B hi/lo: 2*256 rows * 4 u4
            int w = v - 1024;
            int which = w >> 10, idx = w & 1023;
            int row = idx >> 2, u = idx & 3;
            int gate = row >> 6, r = row & 63;
            src = (which ? g_Wlo : g_Whi) + (size_t)(gate * HH + h0 + r) * KKT + k0 + u * 8;
            dst = stage + B_ST + which * BROWS_BYTES + row * RSTRIDE + u * 16;
        }
        cpa16(dst, src);
    }
    CP_COMMIT();
}

// ------------------------------ main kernel --------------------------------

__global__ void __launch_bounds__(256, 1)
lstm_kernel(const float* __restrict__ c_prev,
            const float* __restrict__ b_i, const float* __restrict__ b_f,
            const float* __restrict__ b_g, const float* __restrict__ b_o,
            float* __restrict__ out, int mode) {
    extern __shared__ __align__(128) char smem[];
    uint32_t sb = smem_u32(smem);
    int tid = threadIdx.x;
    int wid = tid >> 5, lane = tid & 31;
    int h0 = blockIdx.x * TNH;
    int m0 = blockIdx.y * TM;

    int gate = wid >> 1;        // 0..3
    int mh   = wid & 1;         // 0..1 (64-row half)

    // ldmatrix lane address components
    int lj = lane >> 3;
    int arofs = (lj & 1) * 8 + (lane & 7);
    int akb   = (lj >> 1) * 16;
    int bnofs = ((lane >> 4) << 3) + (lane & 7);
    int bkb   = ((lane >> 3) & 1) * 16;

    uint32_t a_lane = (uint32_t)((mh * 64 + arofs) * RSTRIDE + akb);
    uint32_t b_lane = (uint32_t)(B_ST + (gate * 64 + bnofs) * RSTRIDE + bkb);

    float acc[4][8][4];
#pragma unroll
    for (int mi = 0; mi < 4; mi++)
#pragma unroll
        for (int nj = 0; nj < 8; nj++)
#pragma unroll
            for (int e = 0; e < 4; e++) acc[mi][nj][e] = 0.0f;

    // prologue: 2 chunks in flight
    load_chunk(sb + 0 * STAGE_BYTES, m0, h0, 0 * KC, tid);
    load_chunk(sb + 1 * STAGE_BYTES, m0, h0, 1 * KC, tid);

    for (int c = 0; c < NCHUNK; c++) {
        if (c + 2 < NCHUNK)
            load_chunk(sb + ((c + 2) % NSTAGE) * STAGE_BYTES, m0, h0, (c + 2) * KC, tid);
        else
            CP_COMMIT();
        CP_WAIT2();
        __syncthreads();

        uint32_t su = sb + (c % NSTAGE) * STAGE_BYTES;
#pragma unroll
        for (int ks = 0; ks < 2; ks++) {
            uint32_t ab = su + a_lane + ks * 32;
            uint32_t bbse = su + b_lane + ks * 32;

            uint32_t ah[4][4], al[4][4], bb[4][4];
#pragma unroll
            for (int mi = 0; mi < 4; mi++) LDSM4(ah[mi], ab + mi * (16 * RSTRIDE));
#pragma unroll
            for (int mi = 0; mi < 4; mi++) LDSM4(al[mi], ab + ALO_ST + mi * (16 * RSTRIDE));
#pragma unroll
            for (int g4 = 0; g4 < 4; g4++) LDSM4(bb[g4], bbse + g4 * (16 * RSTRIDE));

            // term 1: Ahi * Bhi
#pragma unroll
            for (int mi = 0; mi < 4; mi++)
#pragma unroll
                for (int nj = 0; nj < 8; nj++) {
                    int g4 = nj >> 1, hh = (nj & 1) * 2;
                    MMA(acc[mi][nj], ah[mi], bb[g4][hh], bb[g4][hh + 1]);
                }
            // term 2: Alo * Bhi
#pragma unroll
            for (int mi = 0; mi < 4; mi++)
#pragma unroll
                for (int nj = 0; nj < 8; nj++) {
                    int g4 = nj >> 1, hh = (nj & 1) * 2;
                    MMA(acc[mi][nj], al[mi], bb[g4][hh], bb[g4][hh + 1]);
                }
            // reload B = Blo, term 3: Ahi * Blo
#pragma unroll
            for (int g4 = 0; g4 < 4; g4++) LDSM4(bb[g4], bbse + BROWS_BYTES + g4 * (16 * RSTRIDE));
#pragma unroll
            for (int mi = 0; mi < 4; mi++)
#pragma unroll
                for (int nj = 0; nj < 8; nj++) {
                    int g4 = nj >> 1, hh = (nj & 1) * 2;
                    MMA(acc[mi][nj], ah[mi], bb[g4][hh], bb[g4][hh + 1]);
                }
        }
        __syncthreads();
    }

    // ------------------------------ epilogue -------------------------------
    // smem reuse: gates[4][128][66] f32 (135168 B) + bias[256] f32
    float* gsm = (float*)smem;
    float* bs  = (float*)(smem + 4 * 128 * 66 * 4);

    if (tid < 64) {
        bs[tid]       = b_i[h0 + tid];
        bs[64 + tid]  = b_f[h0 + tid];
        bs[128 + tid] = b_g[h0 + tid];
        bs[192 + tid] = b_o[h0 + tid];
    }

    {
        int lr = lane >> 2, lc = (lane & 3) * 2;
        float* gb = gsm + gate * (128 * 66);
#pragma unroll
        for (int mi = 0; mi < 4; mi++) {
            int row = mh * 64 + mi * 16 + lr;
#pragma unroll
            for (int nj = 0; nj < 8; nj++) {
                int col = nj * 8 + lc;
                float* p = gb + row * 66 + col;
                p[0] = acc[mi][nj][0];
                p[1] = acc[mi][nj][1];
                p[8 * 66]     = acc[mi][nj][2];
                p[8 * 66 + 1] = acc[mi][nj][3];
            }
        }
    }
    __syncthreads();

    const size_t BH = (size_t)BB * HH;
#pragma unroll 4
    for (int u = tid; u < TM * TNH; u += 256) {
        int row = u >> 6, col = u & 63;
        size_t off = (size_t)(m0 + row) * HH + h0 + col;
        float gi = gsm[0 * 8448 + row * 66 + col] + bs[col];
        float gf = gsm[1 * 8448 + row * 66 + col] + bs[64 + col];
        float gg = gsm[2 * 8448 + row * 66 + col] + bs[128 + col];
        float go = gsm[3 * 8448 + row * 66 + col] + bs[192 + col];
        float it = sigf(gi), ft = sigf(gf), ot = sigf(go);
        float gt = tanh_fast(gg);
        float cp = c_prev[off];
        float ct = ft * cp + it * gt;
        float ht = ot * tanh_fast(ct);
        if (mode == 3) {
            out[off] = ht; out[BH + off] = ht; out[2 * BH + off] = ct;
        } else if (mode == 2) {
            out[off] = ht; out[BH + off] = ct;
        } else {
            out[off] = ht;
        }
    }
}

// ------------------------------ launch -------------------------------------

extern "C" void kernel_launch(void* const* d_in, const int* in_sizes, int n_in,
                              void* d_out, int out_size) {
    const float* x      = (const float*)d_in[0];
    const float* h_prev = (const float*)d_in[1];
    const float* c_prev = (const float*)d_in[2];
    const float* W_ii = (const float*)d_in[3];
    const float* W_hi = (const float*)d_in[4];
    const float* b_i  = (const float*)d_in[5];
    const float* W_if = (const float*)d_in[6];
    const float* W_hf = (const float*)d_in[7];
    const float* b_f  = (const float*)d_in[8];
    const float* W_ig = (const float*)d_in[9];
    const float* W_hg = (const float*)d_in[10];
    const float* b_g  = (const float*)d_in[11];
    const float* W_io = (const float*)d_in[12];
    const float* W_ho = (const float*)d_in[13];
    const float* b_o  = (const float*)d_in[14];
    float* out = (float*)d_out;

    const long BH = (long)BB * HH;
    int mode = (out_size >= 3 * BH) ? 3 : (out_size >= 2 * BH) ? 2 : 1;

    cudaFuncSetAttribute(lstm_kernel, cudaFuncAttributeMaxDynamicSharedMemorySize, SMEM_TOTAL);

    split_kernel<<<16384, 256>>>(x, h_prev, W_ii, W_if, W_ig, W_io,
                                 W_hi, W_hf, W_hg, W_ho);

    dim3 grid(HH / TNH, BB / TM);   // (16, 32) = 512 CTAs
    lstm_kernel<<<grid, 256, SMEM_TOTAL>>>(c_prev, b_i, b_f, b_g, b_o, out, mode);
}

// round 7
// speedup vs baseline: 1.0596x; 1.0596x over previous
#include <cuda_runtime.h>
#include <cuda_bf16.h>
#include <cstdint>

// ---------------------------------------------------------------------------
// LSTM cell, B=4096, IN=H=1024 (K=2048).
// gates[B,4H] = [x|h] @ [Wx|Wh]^T + b; then elementwise LSTM epilogue.
// mma.sync m16n8k16 bf16 (compute_103-safe), bf16 hi/lo 3-term split,
// cp.async 3-stage pipeline + FRAGMENT double-buffering (ah/bh prefetched one
// phase ahead) to fill the tensor-pipe bubbles seen in R4 (tensor=48.5%).
// ---------------------------------------------------------------------------

#define BB   4096
#define HH   1024
#define KKT  2048
#define TM   128          // rows per CTA
#define TNH  64           // h-cols per CTA (x4 gates = 256 eff cols)
#define KC   32           // K per chunk
#define NCHUNK (KKT / KC) // 64
#define RSTRIDE 80        // smem row stride bytes (64B data + 16B pad)

#define ALO_ST (128 * RSTRIDE)             // 10240
#define B_ST   (2 * 128 * RSTRIDE)         // 20480
#define BROWS_BYTES (256 * RSTRIDE)        // 20480
#define STAGE_BYTES (B_ST + 2 * BROWS_BYTES)  // 61440
#define NSTAGE 3
#define SMEM_TOTAL (STAGE_BYTES * NSTAGE)  // 184320 (epilogue reuses: 136192)

// Pre-split operands (filled each launch; deterministic).
__device__ __nv_bfloat16 g_Ahi[(size_t)BB * KKT];
__device__ __nv_bfloat16 g_Alo[(size_t)BB * KKT];
__device__ __nv_bfloat16 g_Whi[(size_t)4 * HH * KKT];
__device__ __nv_bfloat16 g_Wlo[(size_t)4 * HH * KKT];

// ------------------------------ helpers ------------------------------------

__device__ __forceinline__ uint32_t smem_u32(const void* p) {
    uint32_t a;
    asm("{ .reg .u64 t; cvta.to.shared.u64 t, %1; cvt.u32.u64 %0, t; }" : "=r"(a) : "l"(p));
    return a;
}

__device__ __forceinline__ void cpa16(uint32_t dst, const void* src) {
    asm volatile("cp.async.cg.shared.global [%0], [%1], 16;" :: "r"(dst), "l"(src) : "memory");
}

#define CP_COMMIT() asm volatile("cp.async.commit_group;" ::: "memory")
#define CP_WAIT1()  asm volatile("cp.async.wait_group 1;" ::: "memory")

#define LDSM4(R, ADDR) \
    asm volatile("ldmatrix.sync.aligned.m8n8.x4.shared.b16 {%0,%1,%2,%3}, [%4];" \
                 : "=r"((R)[0]), "=r"((R)[1]), "=r"((R)[2]), "=r"((R)[3]) : "r"(ADDR))

#define MMA(D, A, B0, B1) \
    asm volatile("mma.sync.aligned.m16n8k16.row.col.f32.bf16.bf16.f32 " \
                 "{%0,%1,%2,%3}, {%4,%5,%6,%7}, {%8,%9}, {%0,%1,%2,%3};" \
                 : "+f"((D)[0]), "+f"((D)[1]), "+f"((D)[2]), "+f"((D)[3]) \
                 : "r"((A)[0]), "r"((A)[1]), "r"((A)[2]), "r"((A)[3]), "r"(B0), "r"(B1))

__device__ __forceinline__ float sigf(float x) {
    return __fdividef(1.0f, 1.0f + __expf(-x));
}
__device__ __forceinline__ float tanh_fast(float x) {
    return __fdividef(2.0f, 1.0f + __expf(-2.0f * x)) - 1.0f;
}

// ------------------------- pre-pass: fp32 -> bf16 hi/lo ---------------------
// A region [m,k]: k<1024 -> x, else h_prev. W region [gate,hg,k]: k<1024 -> Wx else Wh.

__global__ void __launch_bounds__(256) split_kernel(
    const float* __restrict__ x, const float* __restrict__ h,
    const float* __restrict__ Wii, const float* __restrict__ Wif,
    const float* __restrict__ Wig, const float* __restrict__ Wio,
    const float* __restrict__ Whi_, const float* __restrict__ Whf,
    const float* __restrict__ Whg, const float* __restrict__ Who) {
    const int AQ = (BB * KKT) / 4;   // float4 units in A region
    int t = blockIdx.x * 256 + threadIdx.x;

    const float* src;
    __nv_bfloat16 *hid, *lod;
    size_t e;
    if (t < AQ) {
        e = (size_t)t * 4;
        int m = t >> 9;
        int k = (int)(e & 2047);
        src = (k < 1024) ? (x + (size_t)m * 1024 + k) : (h + (size_t)m * 1024 + (k - 1024));
        hid = g_Ahi + e; lod = g_Alo + e;
    } else {
        int w = t - AQ;
        e = (size_t)w * 4;
        int gh = w >> 9;
        int k = (int)(e & 2047);
        int gate = gh >> 10;
        int hg = gh & 1023;
        const float* W;
        if (k < 1024) W = (gate == 0) ? Wii : (gate == 1) ? Wif : (gate == 2) ? Wig : Wio;
        else          W = (gate == 0) ? Whi_ : (gate == 1) ? Whf : (gate == 2) ? Whg : Who;
        src = W + (size_t)hg * 1024 + (k & 1023);
        hid = g_Whi + e; lod = g_Wlo + e;
    }

    float4 v = *(const float4*)src;
    float vv[4] = {v.x, v.y, v.z, v.w};
    uint32_t hp[2] = {0, 0}, lp[2] = {0, 0};
#pragma unroll
    for (int i = 0; i < 4; i++) {
        __nv_bfloat16 hb = __float2bfloat16(vv[i]);
        float res = vv[i] - __bfloat162float(hb);
        __nv_bfloat16 lb = __float2bfloat16(res);
        hp[i >> 1] |= (uint32_t)__bfloat16_as_ushort(hb) << ((i & 1) * 16);
        lp[i >> 1] |= (uint32_t)__bfloat16_as_ushort(lb) << ((i & 1) * 16);
    }
    *(uint2*)hid = make_uint2(hp[0], hp[1]);
    *(uint2*)lod = make_uint2(lp[0], lp[1]);
}

// ------------------------------ gmem -> smem -------------------------------

__device__ __forceinline__ void load_chunk(uint32_t stage, int m0, int h0, int k0, int tid) {
#pragma unroll
    for (int j = 0; j < 12; j++) {
        int v = j * 256 + tid;
        const __nv_bfloat16* src;
        uint32_t dst;
        if (v < 1024) {                               // A hi/lo: 2*128 rows * 4 u4
            int which = v >> 9, idx = v & 511;
            int row = idx >> 2, u = idx & 3;
            src = (which ? g_Alo : g_Ahi) + (size_t)(m0 + row) * KKT + k0 + u * 8;
            dst = stage + which * ALO_ST + row * RSTRIDE + u * 16;
        } else {                                      // B hi/lo: 2*256 rows * 4 u4
            int w = v - 1024;
            int which = w >> 10, idx = w & 1023;
            int row = idx >> 2, u = idx & 3;
            int gate = row >> 6, r = row & 63;
            src = (which ? g_Wlo : g_Whi) + (size_t)(gate * HH + h0 + r) * KKT + k0 + u * 8;
            dst = stage + B_ST + which * BROWS_BYTES + row * RSTRIDE + u * 16;
        }
        cpa16(dst, src);
    }
    CP_COMMIT();
}

// ------------------------------ phase body ---------------------------------
// One K=16 phase of the 3-term GEMM. AH/BH were prefetched by the PREVIOUS
// phase; this phase loads its own al/bl (used late: MMA #33 / #65) and
// prefetches NAH/NBH for the next phase from (nA, nB).

__device__ __forceinline__ void phase(
    float (&acc)[4][8][4],
    uint32_t (&AH)[4][4], uint32_t (&BH)[4][4],
    uint32_t (&NAH)[4][4], uint32_t (&NBH)[4][4],
    uint32_t cA, uint32_t cB, uint32_t nA, uint32_t nB) {

    uint32_t al[4][4], bl[4][4];
#pragma unroll
    for (int mi = 0; mi < 4; mi++) LDSM4(al[mi], cA + ALO_ST + mi * (16 * RSTRIDE));
#pragma unroll
    for (int g4 = 0; g4 < 4; g4++) LDSM4(bl[g4], cB + BROWS_BYTES + g4 * (16 * RSTRIDE));
#pragma unroll
    for (int mi = 0; mi < 4; mi++) LDSM4(NAH[mi], nA + mi * (16 * RSTRIDE));
#pragma unroll
    for (int g4 = 0; g4 < 4; g4++) LDSM4(NBH[g4], nB + g4 * (16 * RSTRIDE));

    // term 1: Ahi * Bhi  (operands already resident)
#pragma unroll
    for (int mi = 0; mi < 4; mi++)
#pragma unroll
        for (int nj = 0; nj < 8; nj++) {
            int g4 = nj >> 1, hh = (nj & 1) * 2;
            MMA(acc[mi][nj], AH[mi], BH[g4][hh], BH[g4][hh + 1]);
        }
    // term 2: Alo * Bhi
#pragma unroll
    for (int mi = 0; mi < 4; mi++)
#pragma unroll
        for (int nj = 0; nj < 8; nj++) {
            int g4 = nj >> 1, hh = (nj & 1) * 2;
            MMA(acc[mi][nj], al[mi], BH[g4][hh], BH[g4][hh + 1]);
        }
    // term 3: Ahi * Blo
#pragma unroll
    for (int mi = 0; mi < 4; mi++)
#pragma unroll
        for (int nj = 0; nj < 8; nj++) {
            int g4 = nj >> 1, hh = (nj & 1) * 2;
            MMA(acc[mi][nj], AH[mi], bl[g4][hh], bl[g4][hh + 1]);
        }
}

// ------------------------------ main kernel --------------------------------

__global__ void __launch_bounds__(256, 1)
lstm_kernel(const float* __restrict__ c_prev,
            const float* __restrict__ b_i, const float* __restrict__ b_f,
            const float* __restrict__ b_g, const float* __restrict__ b_o,
            float* __restrict__ out, int mode) {
    extern __shared__ __align__(128) char smem[];
    uint32_t sb = smem_u32(smem);
    int tid = threadIdx.x;
    int wid = tid >> 5, lane = tid & 31;
    int h0 = blockIdx.x * TNH;
    int m0 = blockIdx.y * TM;

    int gate = wid >> 1;        // 0..3
    int mh   = wid & 1;         // 0..1 (64-row half)

    // ldmatrix lane address components
    int lj = lane >> 3;
    int arofs = (lj & 1) * 8 + (lane & 7);
    int akb   = (lj >> 1) * 16;
    int bnofs = ((lane >> 4) << 3) + (lane & 7);
    int bkb   = ((lane >> 3) & 1) * 16;

    uint32_t a_lane = (uint32_t)((mh * 64 + arofs) * RSTRIDE + akb);
    uint32_t b_lane = (uint32_t)(B_ST + (gate * 64 + bnofs) * RSTRIDE + bkb);

    float acc[4][8][4];
#pragma unroll
    for (int mi = 0; mi < 4; mi++)
#pragma unroll
        for (int nj = 0; nj < 8; nj++)
#pragma unroll
            for (int e = 0; e < 4; e++) acc[mi][nj][e] = 0.0f;

    uint32_t ah0[4][4], bh0[4][4], ah1[4][4], bh1[4][4];

    // prologue: 2 chunks in flight; land chunk 0, preload its (0,0) hi frags
    load_chunk(sb + 0 * STAGE_BYTES, m0, h0, 0 * KC, tid);
    load_chunk(sb + 1 * STAGE_BYTES, m0, h0, 1 * KC, tid);
    CP_WAIT1();            // chunk 0 landed (this thread)
    __syncthreads();       // globally visible
    {
        uint32_t su0 = sb;
#pragma unroll
        for (int mi = 0; mi < 4; mi++) LDSM4(ah0[mi], su0 + a_lane + mi * (16 * RSTRIDE));
#pragma unroll
        for (int g4 = 0; g4 < 4; g4++) LDSM4(bh0[g4], su0 + b_lane + g4 * (16 * RSTRIDE));
    }

    for (int c = 0; c < NCHUNK; c++) {
        __syncthreads();   // all reads of stage (c+2)%3's old contents done
        if (c + 2 < NCHUNK)
            load_chunk(sb + ((c + 2) % NSTAGE) * STAGE_BYTES, m0, h0, (c + 2) * KC, tid);
        else
            CP_COMMIT();
        CP_WAIT1();        // chunk c+1 landed (this thread)
        __syncthreads();   // chunk c+1 globally visible

        uint32_t suc = sb + (c % NSTAGE) * STAGE_BYTES;
        uint32_t sun = sb + ((c + 1) % NSTAGE) * STAGE_BYTES;

        // phase A: cur = (c, ks=0) in buf0, prefetch (c, ks=1) into buf1
        phase(acc, ah0, bh0, ah1, bh1,
              suc + a_lane, suc + b_lane,
              suc + a_lane + 32, suc + b_lane + 32);
        // phase B: cur = (c, ks=1) in buf1, prefetch (c+1, ks=0) into buf0
        phase(acc, ah1, bh1, ah0, bh0,
              suc + a_lane + 32, suc + b_lane + 32,
              sun + a_lane, sun + b_lane);
    }

    __syncthreads();

    // ------------------------------ epilogue -------------------------------
    // smem reuse: gates[4][128][66] f32 (135168 B) + bias[256] f32
    float* gsm = (float*)smem;
    float* bs  = (float*)(smem + 4 * 128 * 66 * 4);

    if (tid < 64) {
        bs[tid]       = b_i[h0 + tid];
        bs[64 + tid]  = b_f[h0 + tid];
        bs[128 + tid] = b_g[h0 + tid];
        bs[192 + tid] = b_o[h0 + tid];
    }

    {
        int lr = lane >> 2, lc = (lane & 3) * 2;
        float* gb = gsm + gate * (128 * 66);
#pragma unroll
        for (int mi = 0; mi < 4; mi++) {
            int row = mh * 64 + mi * 16 + lr;
#pragma unroll
            for (int nj = 0; nj < 8; nj++) {
                int col = nj * 8 + lc;
                float* p = gb + row * 66 + col;
                p[0] = acc[mi][nj][0];
                p[1] = acc[mi][nj][1];
                p[8 * 66]     = acc[mi][nj][2];
                p[8 * 66 + 1] = acc[mi][nj][3];
            }
        }
    }
    __syncthreads();

    const size_t BH = (size_t)BB * HH;
#pragma unroll 4
    for (int u = tid; u < TM * TNH; u += 256) {
        int row = u >> 6, col = u & 63;
        size_t off = (size_t)(m0 + row) * HH + h0 + col;
        float gi = gsm[0 * 8448 + row * 66 + col] + bs[col];
        float gf = gsm[1 * 8448 + row * 66 + col] + bs[64 + col];
        float gg = gsm[2 * 8448 + row * 66 + col] + bs[128 + col];
        float go = gsm[3 * 8448 + row * 66 + col] + bs[192 + col];
        float it = sigf(gi), ft = sigf(gf), ot = sigf(go);
        float gt = tanh_fast(gg);
        float cp = c_prev[off];
        float ct = ft * cp + it * gt;
        float ht = ot * tanh_fast(ct);
        if (mode == 3) {
            out[off] = ht; out[BH + off] = ht; out[2 * BH + off] = ct;
        } else if (mode == 2) {
            out[off] = ht; out[BH + off] = ct;
        } else {
            out[off] = ht;
        }
    }
}

// ------------------------------ launch -------------------------------------

extern "C" void kernel_launch(void* const* d_in, const int* in_sizes, int n_in,
                              void* d_out, int out_size) {
    const float* x      = (const float*)d_in[0];
    const float* h_prev = (const float*)d_in[1];
    const float* c_prev = (const float*)d_in[2];
    const float* W_ii = (const float*)d_in[3];
    const float* W_hi = (const float*)d_in[4];
    const float* b_i  = (const float*)d_in[5];
    const float* W_if = (const float*)d_in[6];
    const float* W_hf = (const float*)d_in[7];
    const float* b_f  = (const float*)d_in[8];
    const float* W_ig = (const float*)d_in[9];
    const float* W_hg = (const float*)d_in[10];
    const float* b_g  = (const float*)d_in[11];
    const float* W_io = (const float*)d_in[12];
    const float* W_ho = (const float*)d_in[13];
    const float* b_o  = (const float*)d_in[14];
    float* out = (float*)d_out;

    const long BH = (long)BB * HH;
    int mode = (out_size >= 3 * BH) ? 3 : (out_size >= 2 * BH) ? 2 : 1;

    cudaFuncSetAttribute(lstm_kernel, cudaFuncAttributeMaxDynamicSharedMemorySize, SMEM_TOTAL);

    split_kernel<<<16384, 256>>>(x, h_prev, W_ii, W_if, W_ig, W_io,
                                 W_hi, W_hf, W_hg, W_ho);

    dim3 grid(HH / TNH, BB / TM);   // (16, 32) = 512 CTAs
    lstm_kernel<<<grid, 256, SMEM_TOTAL>>>(c_prev, b_i, b_f, b_g, b_o, out, mode);
}

// round 11
// speedup vs baseline: 2.3920x; 2.2574x over previous
#include <cuda_runtime.h>
#include <cuda_fp16.h>
#include <cstdint>

// ---------------------------------------------------------------------------
// LSTM cell, B=4096, IN=H=1024 (K=2048).
// gates[B,4H] = [x|h] @ [Wx|Wh]^T + b; then elementwise LSTM epilogue.
// SINGLE-TERM fp16 mma.sync m16n8k16 (threshold 1e-3 allows ~4e-4 quantization
// error; R4-R7 measured the 3-term bf16 path at 120x below threshold).
// cp.async 3-stage pipeline, KC=64, fragment double-buffering, fused epilogue.
// ---------------------------------------------------------------------------

#define BB   4096
#define HH   1024
#define KKT  2048
#define TM   128          // rows per CTA
#define TNH  64           // h-cols per CTA (x4 gates = 256 eff cols)
#define KC   64           // K per chunk
#define NCHUNK (KKT / KC) // 32
#define RSTRIDE 144       // 128B data + 16B pad (conflict-free LDSM phases)

#define A_BYTES (128 * RSTRIDE)            // 18432
#define STAGE_BYTES (A_BYTES + 256 * RSTRIDE)  // 55296
#define NSTAGE 3
#define SMEM_TOTAL (STAGE_BYTES * NSTAGE)  // 165888 (epilogue reuses 136192)

// Pre-converted fp16 operands (filled each launch; deterministic).
__device__ __half g_Ah[(size_t)BB * KKT];
__device__ __half g_Wh[(size_t)4 * HH * KKT];

// ------------------------------ helpers ------------------------------------

__device__ __forceinline__ uint32_t smem_u32(const void* p) {
    uint32_t a;
    asm("{ .reg .u64 t; cvta.to.shared.u64 t, %1; cvt.u32.u64 %0, t; }" : "=r"(a) : "l"(p));
    return a;
}

__device__ __forceinline__ void cpa16(uint32_t dst, const void* src) {
    asm volatile("cp.async.cg.shared.global [%0], [%1], 16;" :: "r"(dst), "l"(src) : "memory");
}

#define CP_COMMIT() asm volatile("cp.async.commit_group;" ::: "memory")
#define CP_WAIT1()  asm volatile("cp.async.wait_group 1;" ::: "memory")

#define LDSM4(R, ADDR) \
    asm volatile("ldmatrix.sync.aligned.m8n8.x4.shared.b16 {%0,%1,%2,%3}, [%4];" \
                 : "=r"((R)[0]), "=r"((R)[1]), "=r"((R)[2]), "=r"((R)[3]) : "r"(ADDR))

#define MMA(D, A, B0, B1) \
    asm volatile("mma.sync.aligned.m16n8k16.row.col.f32.f16.f16.f32 " \
                 "{%0,%1,%2,%3}, {%4,%5,%6,%7}, {%8,%9}, {%0,%1,%2,%3};" \
                 : "+f"((D)[0]), "+f"((D)[1]), "+f"((D)[2]), "+f"((D)[3]) \
                 : "r"((A)[0]), "r"((A)[1]), "r"((A)[2]), "r"((A)[3]), "r"(B0), "r"(B1))

__device__ __forceinline__ float sigf(float x) {
    return __fdividef(1.0f, 1.0f + __expf(-x));
}
__device__ __forceinline__ float tanh_fast(float x) {
    return __fdividef(2.0f, 1.0f + __expf(-2.0f * x)) - 1.0f;
}

// ------------------------- pre-pass: fp32 -> fp16 ---------------------------
// A region [m,k]: k<1024 -> x, else h_prev. W region [gate,hg,k]: k<1024 -> Wx else Wh.

__global__ void __launch_bounds__(256) split_kernel(
    const float* __restrict__ x, const float* __restrict__ h,
    const float* __restrict__ Wii, const float* __restrict__ Wif,
    const float* __restrict__ Wig, const float* __restrict__ Wio,
    const float* __restrict__ Whi_, const float* __restrict__ Whf,
    const float* __restrict__ Whg, const float* __restrict__ Who) {
    const int AQ = (BB * KKT) / 4;   // float4 units in A region
    int t = blockIdx.x * 256 + threadIdx.x;

    const float* src;
    __half* dst;
    size_t e;
    if (t < AQ) {
        e = (size_t)t * 4;
        int m = t >> 9;
        int k = (int)(e & 2047);
        src = (k < 1024) ? (x + (size_t)m * 1024 + k) : (h + (size_t)m * 1024 + (k - 1024));
        dst = g_Ah + e;
    } else {
        int w = t - AQ;
        e = (size_t)w * 4;
        int gh = w >> 9;
        int k = (int)(e & 2047);
        int gate = gh >> 10;
        int hg = gh & 1023;
        const float* W;
        if (k < 1024) W = (gate == 0) ? Wii : (gate == 1) ? Wif : (gate == 2) ? Wig : Wio;
        else          W = (gate == 0) ? Whi_ : (gate == 1) ? Whf : (gate == 2) ? Whg : Who;
        src = W + (size_t)hg * 1024 + (k & 1023);
        dst = g_Wh + e;
    }

    float4 v = *(const float4*)src;
    __half2 p0 = __floats2half2_rn(v.x, v.y);
    __half2 p1 = __floats2half2_rn(v.z, v.w);
    uint2 out;
    out.x = *(const uint32_t*)&p0;
    out.y = *(const uint32_t*)&p1;
    *(uint2*)dst = out;
}

// ------------------------------ gmem -> smem -------------------------------
// Per chunk: A 128 rows x 128B, B 256 rows x 128B -> 3072 cpa16, 12/thread.

__device__ __forceinline__ void load_chunk(uint32_t stage, int m0, int h0, int k0, int tid) {
#pragma unroll
    for (int j = 0; j < 12; j++) {
        int v = j * 256 + tid;
        const __half* src;
        uint32_t dst;
        if (v < 1024) {                               // A: 128 rows x 8 u4
            int row = v >> 3, u = v & 7;
            src = g_Ah + (size_t)(m0 + row) * KKT + k0 + u * 8;
            dst = stage + row * RSTRIDE + u * 16;
        } else {                                      // B: 256 rows x 8 u4
            int w = v - 1024;
            int row = w >> 3, u = w & 7;
            int gate = row >> 6, r = row & 63;
            src = g_Wh + (size_t)(gate * HH + h0 + r) * KKT + k0 + u * 8;
            dst = stage + A_BYTES + row * RSTRIDE + u * 16;
        }
        cpa16(dst, src);
    }
    CP_COMMIT();
}

// ------------------------------ phase body ---------------------------------
// One K=16 phase. AH/BB were prefetched by the previous phase; this phase
// prefetches NAH/NBB for the next phase from (nA, nB) and runs 32 MMAs.

__device__ __forceinline__ void phase(
    float (&acc)[4][8][4],
    uint32_t (&AH)[4][4], uint32_t (&BBf)[4][4],
    uint32_t (&NAH)[4][4], uint32_t (&NBB)[4][4],
    uint32_t nA, uint32_t nB) {

#pragma unroll
    for (int mi = 0; mi < 4; mi++) LDSM4(NAH[mi], nA + mi * (16 * RSTRIDE));
#pragma unroll
    for (int g4 = 0; g4 < 4; g4++) LDSM4(NBB[g4], nB + g4 * (16 * RSTRIDE));

#pragma unroll
    for (int mi = 0; mi < 4; mi++)
#pragma unroll
        for (int nj = 0; nj < 8; nj++) {
            int g4 = nj >> 1, hh = (nj & 1) * 2;
            MMA(acc[mi][nj], AH[mi], BBf[g4][hh], BBf[g4][hh + 1]);
        }
}

// ------------------------------ main kernel --------------------------------

__global__ void __launch_bounds__(256, 1)
lstm_kernel(const float* __restrict__ c_prev,
            const float* __restrict__ b_i, const float* __restrict__ b_f,
            const float* __restrict__ b_g, const float* __restrict__ b_o,
            float* __restrict__ out, int mode) {
    extern __shared__ __align__(128) char smem[];
    uint32_t sb = smem_u32(smem);
    int tid = threadIdx.x;
    int wid = tid >> 5, lane = tid & 31;
    int h0 = blockIdx.x * TNH;
    int m0 = blockIdx.y * TM;

    int gate = wid >> 1;        // 0..3
    int mh   = wid & 1;         // 0..1 (64-row half)

    // ldmatrix lane address components
    int lj = lane >> 3;
    int arofs = (lj & 1) * 8 + (lane & 7);
    int akb   = (lj >> 1) * 16;
    int bnofs = ((lane >> 4) << 3) + (lane & 7);
    int bkb   = ((lane >> 3) & 1) * 16;

    uint32_t a_lane = (uint32_t)((mh * 64 + arofs) * RSTRIDE + akb);
    uint32_t b_lane = (uint32_t)(A_BYTES + (gate * 64 + bnofs) * RSTRIDE + bkb);

    float acc[4][8][4];
#pragma unroll
    for (int mi = 0; mi < 4; mi++)
#pragma unroll
        for (int nj = 0; nj < 8; nj++)
#pragma unroll
            for (int e = 0; e < 4; e++) acc[mi][nj][e] = 0.0f;

    uint32_t ah0[4][4], bb0[4][4], ah1[4][4], bb1[4][4];

    // prologue: 2 chunks in flight; land chunk 0, preload its (ks=0) frags
    load_chunk(sb + 0 * STAGE_BYTES, m0, h0, 0 * KC, tid);
    load_chunk(sb + 1 * STAGE_BYTES, m0, h0, 1 * KC, tid);
    CP_WAIT1();            // chunk 0 landed (this thread)
    __syncthreads();       // globally visible
    {
#pragma unroll
        for (int mi = 0; mi < 4; mi++) LDSM4(ah0[mi], sb + a_lane + mi * (16 * RSTRIDE));
#pragma unroll
        for (int g4 = 0; g4 < 4; g4++) LDSM4(bb0[g4], sb + b_lane + g4 * (16 * RSTRIDE));
    }

    for (int c = 0; c < NCHUNK; c++) {
        __syncthreads();   // all reads of stage (c+2)%3's old contents done
        if (c + 2 < NCHUNK)
            load_chunk(sb + ((c + 2) % NSTAGE) * STAGE_BYTES, m0, h0, (c + 2) * KC, tid);
        else
            CP_COMMIT();
        CP_WAIT1();        // chunk c+1 landed (this thread)
        __syncthreads();   // chunk c+1 globally visible

        uint32_t suc = sb + (c % NSTAGE) * STAGE_BYTES;
        uint32_t sun = sb + ((c + 1) % NSTAGE) * STAGE_BYTES;

        // 4 K=16 phases; buffers alternate 0,1,0,1; last prefetches next chunk
        phase(acc, ah0, bb0, ah1, bb1, suc + a_lane + 32, suc + b_lane + 32);
        phase(acc, ah1, bb1, ah0, bb0, suc + a_lane + 64, suc + b_lane + 64);
        phase(acc, ah0, bb0, ah1, bb1, suc + a_lane + 96, suc + b_lane + 96);
        phase(acc, ah1, bb1, ah0, bb0, sun + a_lane, sun + b_lane);
    }

    __syncthreads();

    // ------------------------------ epilogue -------------------------------
    // smem reuse: gates[4][128][66] f32 (135168 B) + bias[256] f32
    float* gsm = (float*)smem;
    float* bs  = (float*)(smem + 4 * 128 * 66 * 4);

    if (tid < 64) {
        bs[tid]       = b_i[h0 + tid];
        bs[64 + tid]  = b_f[h0 + tid];
        bs[128 + tid] = b_g[h0 + tid];
        bs[192 + tid] = b_o[h0 + tid];
    }

    {
        int lr = lane >> 2, lc = (lane & 3) * 2;
        float* gb = gsm + gate * (128 * 66);
#pragma unroll
        for (int mi = 0; mi < 4; mi++) {
            int row = mh * 64 + mi * 16 + lr;
#pragma unroll
            for (int nj = 0; nj < 8; nj++) {
                int col = nj * 8 + lc;
                float* p = gb + row * 66 + col;
                p[0] = acc[mi][nj][0];
                p[1] = acc[mi][nj][1];
                p[8 * 66]     = acc[mi][nj][2];
                p[8 * 66 + 1] = acc[mi][nj][3];
            }
        }
    }
    __syncthreads();

    const size_t BH = (size_t)BB * HH;
#pragma unroll 4
    for (int u = tid; u < TM * TNH; u += 256) {
        int row = u >> 6, col = u & 63;
        size_t off = (size_t)(m0 + row) * HH + h0 + col;
        float gi = gsm[0 * 8448 + row * 66 + col] + bs[col];
        float gf = gsm[1 * 8448 + row * 66 + col] + bs[64 + col];
        float gg = gsm[2 * 8448 + row * 66 + col] + bs[128 + col];
        float go = gsm[3 * 8448 + row * 66 + col] + bs[192 + col];
        float it = sigf(gi), ft = sigf(gf), ot = sigf(go);
        float gt = tanh_fast(gg);
        float cp = c_prev[off];
        float ct = ft * cp + it * gt;
        float ht = ot * tanh_fast(ct);
        if (mode == 3) {
            out[off] = ht; out[BH + off] = ht; out[2 * BH + off] = ct;
        } else if (mode == 2) {
            out[off] = ht; out[BH + off] = ct;
        } else {
            out[off] = ht;
        }
    }
}

// ------------------------------ launch -------------------------------------

extern "C" void kernel_launch(void* const* d_in, const int* in_sizes, int n_in,
                              void* d_out, int out_size) {
    const float* x      = (const float*)d_in[0];
    const float* h_prev = (const float*)d_in[1];
    const float* c_prev = (const float*)d_in[2];
    const float* W_ii = (const float*)d_in[3];
    const float* W_hi = (const float*)d_in[4];
    const float* b_i  = (const float*)d_in[5];
    const float* W_if = (const float*)d_in[6];
    const float* W_hf = (const float*)d_in[7];
    const float* b_f  = (const float*)d_in[8];
    const float* W_ig = (const float*)d_in[9];
    const float* W_hg = (const float*)d_in[10];
    const float* b_g  = (const float*)d_in[11];
    const float* W_io = (const float*)d_in[12];
    const float* W_ho = (const float*)d_in[13];
    const float* b_o  = (const float*)d_in[14];
    float* out = (float*)d_out;

    const long BH = (long)BB * HH;
    int mode = (out_size >= 3 * BH) ? 3 : (out_size >= 2 * BH) ? 2 : 1;

    cudaFuncSetAttribute(lstm_kernel, cudaFuncAttributeMaxDynamicSharedMemorySize, SMEM_TOTAL);

    // total float4 units = (BB*KKT + 4*HH*KKT) / 4 = 4194304 -> 16384 blocks
    split_kernel<<<16384, 256>>>(x, h_prev, W_ii, W_if, W_ig, W_io,
                                 W_hi, W_hf, W_hg, W_ho);

    dim3 grid(HH / TNH, BB / TM);   // (16, 32) = 512 CTAs
    lstm_kernel<<<grid, 256, SMEM_TOTAL>>>(c_prev, b_i, b_f, b_g, b_o, out, mode);
}